// round 9
// baseline (speedup 1.0000x reference)
#include <cuda_runtime.h>
#include <math_constants.h>

// Fixed problem shape: [16, 17, 384, 384] fp32
#define HM_W 384
#define HM_H 384
#define HM_PLANES 272
#define BAND 32
#define BANDS (HM_H / BAND)          // 12
#define WARPS 2
#define TPB (WARPS * 32)             // 64
#define NUNITS (HM_PLANES * BANDS)   // 3264
#define NBLOCKS (NUNITS / WARPS)     // 1632

#define PF_DIST 4                    // prefetch distance in rows

#define SIG_THRESH 0.05f
// logit(0.05): sigmoid(x) > 0.05  <=>  x > LOGIT_THRESH
#define LOGIT_THRESH (-2.9444389791664403f)
#define FULLM 0xffffffffu

__device__ __forceinline__ float max3(float a, float b, float c) {
    return fmaxf(a, fmaxf(b, c));
}

__device__ __forceinline__ float4 max3v(const float4& a, const float4& b, const float4& c) {
    float4 r;
    r.x = max3(a.x, b.x, c.x);
    r.y = max3(a.y, b.y, c.y);
    r.z = max3(a.z, b.z, c.z);
    r.w = max3(a.w, b.w, c.w);
    return r;
}

// peak score: sigmoid(x) if (3x3 max == x) && x > logit(0.05), else 0
__device__ __forceinline__ float peak(float m, float x) {
    float e = __expf(-x);
    float s = __fdividef(1.0f, 1.0f + e);
    return (m == x && x > LOGIT_THRESH) ? s : 0.0f;
}

__device__ __forceinline__ float4 peaks4(const float4& c, const float4& v,
                                         float vl, float vr) {
    float4 r;
    r.x = peak(max3(vl,  v.x, v.y), c.x);
    r.y = peak(max3(v.x, v.y, v.z), c.y);
    r.z = peak(max3(v.y, v.z, v.w), c.z);
    r.w = peak(max3(v.z, v.w, vr),  c.w);
    return r;
}

__device__ __forceinline__ void pf_l2(const float* p) {
    asm volatile("prefetch.global.L2 [%0];" :: "l"(p));
}

__global__ __launch_bounds__(TPB, 11)
void heatmap_peaks_kernel(const float* __restrict__ in, float* __restrict__ out) {
    const int lane = threadIdx.x & 31;
    const int warp = threadIdx.x >> 5;
    const int unit = blockIdx.x * WARPS + warp;

    const int plane = unit / BANDS;
    const int band  = unit - plane * BANDS;

    const float* __restrict__ p = in  + (size_t)plane * (HM_W * HM_H);
    float* __restrict__       o = out + (size_t)plane * (HM_W * HM_H);

    const int r0 = band * BAND;
    const int xb = lane * 4;           // interleaved: cols xb, xb+128, xb+256
    const float NEG = -CUDART_INF_F;
    const float4 NEG4 = make_float4(NEG, NEG, NEG, NEG);

    // Carried rows P (prev), C (cur). 3 coalesced float4 chunks each.
    float4 P0, P1, P2, C0, C1, C2;

    if (r0 > 0) {
        const float* rp = p + (size_t)(r0 - 1) * HM_W + xb;
        P0 = *(const float4*)(rp);
        P1 = *(const float4*)(rp + 128);
        P2 = *(const float4*)(rp + 256);
    } else {
        P0 = NEG4; P1 = NEG4; P2 = NEG4;
    }
    {
        const float* rp = p + (size_t)r0 * HM_W + xb;
        C0 = *(const float4*)(rp);
        C1 = *(const float4*)(rp + 128);
        C2 = *(const float4*)(rp + 256);
    }

    const float* np = p + (size_t)(r0 + 1) * HM_W + xb;   // next-row pointer
    float*       op = o + (size_t)r0 * HM_W + xb;         // output-row pointer

    #pragma unroll 4
    for (int r = r0; r < r0 + BAND; ++r) {
        // L2 prefetch PF_DIST rows ahead (no registers, no scoreboard).
        // Clamped to the plane's last row: never out of bounds; re-touching
        // a resident line is harmless. Over-run past the band halo warms
        // the next band's rows — cross-block useful, not wasted.
        {
            int pr = r + 1 + PF_DIST;
            pr = (pr < HM_H) ? pr : (HM_H - 1);
            const float* fq = p + (size_t)pr * HM_W + xb;
            pf_l2(fq);
            pf_l2(fq + 128);
            pf_l2(fq + 256);
        }

        // Load next row (demand stream)
        float4 N0, N1, N2;
        if (r + 1 < HM_H) {
            N0 = *(const float4*)(np);
            N1 = *(const float4*)(np + 128);
            N2 = *(const float4*)(np + 256);
        } else {
            N0 = NEG4; N1 = NEG4; N2 = NEG4;
        }
        np += HM_W;

        // Vertical 3-max per column
        float4 v0 = max3v(P0, C0, N0);
        float4 v1 = max3v(P1, C1, N1);
        float4 v2 = max3v(P2, C2, N2);

        // Horizontal neighbors via warp shuffles.
        float l0 = __shfl_up_sync(FULLM, v0.w, 1);
        float l1 = __shfl_up_sync(FULLM, v1.w, 1);
        float l2 = __shfl_up_sync(FULLM, v2.w, 1);
        float b01 = __shfl_sync(FULLM, v0.w, 31);
        float b12 = __shfl_sync(FULLM, v1.w, 31);
        float r0s = __shfl_down_sync(FULLM, v0.x, 1);
        float r1s = __shfl_down_sync(FULLM, v1.x, 1);
        float r2s = __shfl_down_sync(FULLM, v2.x, 1);
        float f10 = __shfl_sync(FULLM, v1.x, 0);
        float f21 = __shfl_sync(FULLM, v2.x, 0);

        if (lane == 0)  { l0 = NEG; l1 = b01; l2 = b12; }
        if (lane == 31) { r0s = f10; r1s = f21; r2s = NEG; }

        // Peak test + sigmoid, store row
        float4 o0 = peaks4(C0, v0, l0, r0s);
        float4 o1 = peaks4(C1, v1, l1, r1s);
        float4 o2 = peaks4(C2, v2, l2, r2s);

        *(float4*)(op)       = o0;
        *(float4*)(op + 128) = o1;
        *(float4*)(op + 256) = o2;
        op += HM_W;

        // Rotate carried rows
        P0 = C0; P1 = C1; P2 = C2;
        C0 = N0; C1 = N1; C2 = N2;
    }
}

extern "C" void kernel_launch(void* const* d_in, const int* in_sizes, int n_in,
                              void* d_out, int out_size) {
    (void)in_sizes; (void)n_in; (void)out_size;
    const float* heatmaps = (const float*)d_in[0];
    float* out = (float*)d_out;

    heatmap_peaks_kernel<<<NBLOCKS, TPB>>>(heatmaps, out);
}

// round 10
// speedup vs baseline: 1.1888x; 1.1888x over previous
#include <cuda_runtime.h>
#include <math_constants.h>

// Fixed problem shape: [16, 17, 384, 384] fp32
#define HM_W 384
#define HM_H 384
#define HM_PLANES 272
#define BAND 32
#define BANDS (HM_H / BAND)          // 12
#define WARPS 2
#define TPB (WARPS * 32)             // 64
#define NUNITS (HM_PLANES * BANDS)   // 3264
#define NBLOCKS (NUNITS / WARPS)     // 1632

#define SIG_THRESH 0.05f
// logit(0.05): sigmoid(x) > 0.05  <=>  x > LOGIT_THRESH
#define LOGIT_THRESH (-2.9444389791664403f)
#define FULLM 0xffffffffu

__device__ __forceinline__ float max3(float a, float b, float c) {
    return fmaxf(a, fmaxf(b, c));
}

__device__ __forceinline__ float4 max3v(const float4& a, const float4& b, const float4& c) {
    float4 r;
    r.x = max3(a.x, b.x, c.x);
    r.y = max3(a.y, b.y, c.y);
    r.z = max3(a.z, b.z, c.z);
    r.w = max3(a.w, b.w, c.w);
    return r;
}

// peak score: sigmoid(x) if (3x3 max == x) && x > logit(0.05), else 0
__device__ __forceinline__ float peak(float m, float x) {
    float e = __expf(-x);
    float s = __fdividef(1.0f, 1.0f + e);
    return (m == x && x > LOGIT_THRESH) ? s : 0.0f;
}

__device__ __forceinline__ float4 peaks4(const float4& c, const float4& v,
                                         float vl, float vr) {
    float4 r;
    r.x = peak(max3(vl,  v.x, v.y), c.x);
    r.y = peak(max3(v.x, v.y, v.z), c.y);
    r.z = peak(max3(v.y, v.z, v.w), c.z);
    r.w = peak(max3(v.z, v.w, vr),  c.w);
    return r;
}

__global__ __launch_bounds__(TPB, 11)
void heatmap_peaks_kernel(const float* __restrict__ in, float* __restrict__ out) {
    const int lane = threadIdx.x & 31;
    const int warp = threadIdx.x >> 5;
    const int unit = blockIdx.x * WARPS + warp;

    const int plane = unit / BANDS;
    const int band  = unit - plane * BANDS;

    const float* __restrict__ p = in  + (size_t)plane * (HM_W * HM_H);
    float* __restrict__       o = out + (size_t)plane * (HM_W * HM_H);

    const int r0 = band * BAND;
    const int xb = lane * 4;           // interleaved: cols xb, xb+128, xb+256
    const float NEG = -CUDART_INF_F;
    const float4 NEG4 = make_float4(NEG, NEG, NEG, NEG);

    // Carried rows P (prev), C (cur). 3 coalesced float4 chunks each.
    float4 P0, P1, P2, C0, C1, C2;

    if (r0 > 0) {
        const float4* rp = (const float4*)(p + (size_t)(r0 - 1) * HM_W + xb);
        P0 = __ldcs(rp);
        P1 = __ldcs(rp + 32);
        P2 = __ldcs(rp + 64);
    } else {
        P0 = NEG4; P1 = NEG4; P2 = NEG4;
    }
    {
        const float4* rp = (const float4*)(p + (size_t)r0 * HM_W + xb);
        C0 = __ldcs(rp);
        C1 = __ldcs(rp + 32);
        C2 = __ldcs(rp + 64);
    }

    const float* np = p + (size_t)(r0 + 1) * HM_W + xb;   // next-row pointer
    float*       op = o + (size_t)r0 * HM_W + xb;         // output-row pointer

    #pragma unroll 4
    for (int r = r0; r < r0 + BAND; ++r) {
        // Load next row (streaming: lines are single-use)
        float4 N0, N1, N2;
        if (r + 1 < HM_H) {
            const float4* rp = (const float4*)np;
            N0 = __ldcs(rp);
            N1 = __ldcs(rp + 32);
            N2 = __ldcs(rp + 64);
        } else {
            N0 = NEG4; N1 = NEG4; N2 = NEG4;
        }
        np += HM_W;

        // Vertical 3-max per column
        float4 v0 = max3v(P0, C0, N0);
        float4 v1 = max3v(P1, C1, N1);
        float4 v2 = max3v(P2, C2, N2);

        // Horizontal neighbors via warp shuffles.
        float l0 = __shfl_up_sync(FULLM, v0.w, 1);
        float l1 = __shfl_up_sync(FULLM, v1.w, 1);
        float l2 = __shfl_up_sync(FULLM, v2.w, 1);
        float b01 = __shfl_sync(FULLM, v0.w, 31);
        float b12 = __shfl_sync(FULLM, v1.w, 31);
        float r0s = __shfl_down_sync(FULLM, v0.x, 1);
        float r1s = __shfl_down_sync(FULLM, v1.x, 1);
        float r2s = __shfl_down_sync(FULLM, v2.x, 1);
        float f10 = __shfl_sync(FULLM, v1.x, 0);
        float f21 = __shfl_sync(FULLM, v2.x, 0);

        if (lane == 0)  { l0 = NEG; l1 = b01; l2 = b12; }
        if (lane == 31) { r0s = f10; r1s = f21; r2s = NEG; }

        // Peak test + sigmoid, store row (streaming: never re-read)
        float4 o0 = peaks4(C0, v0, l0, r0s);
        float4 o1 = peaks4(C1, v1, l1, r1s);
        float4 o2 = peaks4(C2, v2, l2, r2s);

        __stcs((float4*)(op),       o0);
        __stcs((float4*)(op + 128), o1);
        __stcs((float4*)(op + 256), o2);
        op += HM_W;

        // Rotate carried rows
        P0 = C0; P1 = C1; P2 = C2;
        C0 = N0; C1 = N1; C2 = N2;
    }
}

extern "C" void kernel_launch(void* const* d_in, const int* in_sizes, int n_in,
                              void* d_out, int out_size) {
    (void)in_sizes; (void)n_in; (void)out_size;
    const float* heatmaps = (const float*)d_in[0];
    float* out = (float*)d_out;

    heatmap_peaks_kernel<<<NBLOCKS, TPB>>>(heatmaps, out);
}

// round 11
// speedup vs baseline: 1.2759x; 1.0733x over previous
#include <cuda_runtime.h>
#include <math_constants.h>
#include <cstdint>

// Fixed problem shape: [16, 17, 384, 384] fp32
#define HM_W 384
#define HM_H 384
#define HM_PLANES 272
#define BAND 24
#define BANDS (HM_H / BAND)            // 16
#define TPB 128                        // 4 warps
#define ROWS_PER_WARP (BAND / 4)       // 6
#define TILE_ROWS (BAND + 2)           // 26 (band + top/bottom halo)
#define NBLOCKS (HM_PLANES * BANDS)    // 4352

#define SIG_THRESH 0.05f
// logit(0.05): sigmoid(x) > 0.05  <=>  x > LOGIT_THRESH
#define LOGIT_THRESH (-2.9444389791664403f)
#define FULLM 0xffffffffu

__device__ __forceinline__ float max3(float a, float b, float c) {
    return fmaxf(a, fmaxf(b, c));
}

__device__ __forceinline__ float4 max3v(const float4& a, const float4& b, const float4& c) {
    float4 r;
    r.x = max3(a.x, b.x, c.x);
    r.y = max3(a.y, b.y, c.y);
    r.z = max3(a.z, b.z, c.z);
    r.w = max3(a.w, b.w, c.w);
    return r;
}

// peak score: sigmoid(x) if (3x3 max == x) && x > logit(0.05), else 0
__device__ __forceinline__ float peak(float m, float x) {
    float e = __expf(-x);
    float s = __fdividef(1.0f, 1.0f + e);
    return (m == x && x > LOGIT_THRESH) ? s : 0.0f;
}

__device__ __forceinline__ float4 peaks4(const float4& c, const float4& v,
                                         float vl, float vr) {
    float4 r;
    r.x = peak(max3(vl,  v.x, v.y), c.x);
    r.y = peak(max3(v.x, v.y, v.z), c.y);
    r.z = peak(max3(v.y, v.z, v.w), c.z);
    r.w = peak(max3(v.z, v.w, vr),  c.w);
    return r;
}

__device__ __forceinline__ uint32_t smem_u32(const void* p) {
    uint32_t a;
    asm("{ .reg .u64 t; cvta.to.shared.u64 t, %1; cvt.u32.u64 %0, t; }"
        : "=r"(a) : "l"(p));
    return a;
}

__global__ __launch_bounds__(TPB)
void heatmap_peaks_kernel(const float* __restrict__ in, float* __restrict__ out) {
    __shared__ __align__(16) float tile[TILE_ROWS * HM_W];  // 39936 B
    __shared__ uint64_t mbar;

    const int tid  = threadIdx.x;
    const int lane = tid & 31;
    const int warp = tid >> 5;

    const int plane = blockIdx.x / BANDS;
    const int band  = blockIdx.x - plane * BANDS;
    const int r0    = band * BAND;

    const float* __restrict__ p = in  + (size_t)plane * (HM_W * HM_H);
    float* __restrict__       o = out + (size_t)plane * (HM_W * HM_H);

    // Contiguous copy range: rows [rs, re] of this plane (band + available halo)
    const int rs = (r0 > 0) ? (r0 - 1) : 0;
    const int re_ = r0 + BAND;                       // want rows up to r0+BAND (bottom halo)
    const int re = (re_ < HM_H) ? re_ : (HM_H - 1);
    const int nrows = re - rs + 1;
    const int slot0 = rs - (r0 - 1);                 // 0 normally, 1 for the top band
    const uint32_t bytes = (uint32_t)nrows * HM_W * sizeof(float);

    const uint32_t mbar_a = smem_u32(&mbar);
    const uint32_t dst_a  = smem_u32(&tile[slot0 * HM_W]);

    if (tid == 0) {
        asm volatile("mbarrier.init.shared.b64 [%0], %1;"
                     :: "r"(mbar_a), "r"(1) : "memory");
    }
    __syncthreads();

    if (tid == 0) {
        asm volatile("mbarrier.arrive.expect_tx.shared.b64 _, [%0], %1;"
                     :: "r"(mbar_a), "r"(bytes) : "memory");
        asm volatile("cp.async.bulk.shared::cluster.global.mbarrier::complete_tx::bytes "
                     "[%0], [%1], %2, [%3];"
                     :: "r"(dst_a), "l"(p + (size_t)rs * HM_W), "r"(bytes), "r"(mbar_a)
                     : "memory");
    }

    // Wait for the bulk copy (phase 0)
    {
        uint32_t done;
        asm volatile(
            "{\n\t"
            ".reg .pred q;\n\t"
            "mbarrier.try_wait.parity.acquire.cta.shared::cta.b64 q, [%1], 0;\n\t"
            "selp.b32 %0, 1, 0, q;\n\t"
            "}"
            : "=r"(done) : "r"(mbar_a) : "memory");
        while (!done) {
            asm volatile(
                "{\n\t"
                ".reg .pred q;\n\t"
                "mbarrier.try_wait.parity.acquire.cta.shared::cta.b64 q, [%1], 0, 0x989680;\n\t"
                "selp.b32 %0, 1, 0, q;\n\t"
                "}"
                : "=r"(done) : "r"(mbar_a) : "memory");
        }
    }

    // ---- compute from SMEM: warp w handles rows [r0+6w, r0+6w+6) ----
    const int wr = r0 + ROWS_PER_WARP * warp;        // first output row of this warp
    const int baseSlot = ROWS_PER_WARP * warp;       // smem slot of row wr-1
    const int xb = lane * 4;                         // interleaved: cols xb, xb+128, xb+256
    const float NEG = -CUDART_INF_F;
    const float4 NEG4 = make_float4(NEG, NEG, NEG, NEG);

    float4 P0, P1, P2, C0, C1, C2;
    if (wr > 0) {
        const float* t = &tile[baseSlot * HM_W + xb];
        P0 = *(const float4*)(t);
        P1 = *(const float4*)(t + 128);
        P2 = *(const float4*)(t + 256);
    } else {
        P0 = NEG4; P1 = NEG4; P2 = NEG4;
    }
    {
        const float* t = &tile[(baseSlot + 1) * HM_W + xb];
        C0 = *(const float4*)(t);
        C1 = *(const float4*)(t + 128);
        C2 = *(const float4*)(t + 256);
    }

    float* op = o + (size_t)wr * HM_W + xb;

    #pragma unroll
    for (int i = 0; i < ROWS_PER_WARP; ++i) {
        const int row = wr + i;

        float4 N0, N1, N2;
        if (row + 1 < HM_H) {
            const float* t = &tile[(baseSlot + 2 + i) * HM_W + xb];
            N0 = *(const float4*)(t);
            N1 = *(const float4*)(t + 128);
            N2 = *(const float4*)(t + 256);
        } else {
            N0 = NEG4; N1 = NEG4; N2 = NEG4;
        }

        // Vertical 3-max per column
        float4 v0 = max3v(P0, C0, N0);
        float4 v1 = max3v(P1, C1, N1);
        float4 v2 = max3v(P2, C2, N2);

        // Horizontal neighbors via warp shuffles
        float l0 = __shfl_up_sync(FULLM, v0.w, 1);
        float l1 = __shfl_up_sync(FULLM, v1.w, 1);
        float l2 = __shfl_up_sync(FULLM, v2.w, 1);
        float b01 = __shfl_sync(FULLM, v0.w, 31);
        float b12 = __shfl_sync(FULLM, v1.w, 31);
        float r0s = __shfl_down_sync(FULLM, v0.x, 1);
        float r1s = __shfl_down_sync(FULLM, v1.x, 1);
        float r2s = __shfl_down_sync(FULLM, v2.x, 1);
        float f10 = __shfl_sync(FULLM, v1.x, 0);
        float f21 = __shfl_sync(FULLM, v2.x, 0);

        if (lane == 0)  { l0 = NEG; l1 = b01; l2 = b12; }
        if (lane == 31) { r0s = f10; r1s = f21; r2s = NEG; }

        // Peak test + sigmoid, store row
        float4 o0 = peaks4(C0, v0, l0, r0s);
        float4 o1 = peaks4(C1, v1, l1, r1s);
        float4 o2 = peaks4(C2, v2, l2, r2s);

        *(float4*)(op)       = o0;
        *(float4*)(op + 128) = o1;
        *(float4*)(op + 256) = o2;
        op += HM_W;

        // Rotate carried rows
        P0 = C0; P1 = C1; P2 = C2;
        C0 = N0; C1 = N1; C2 = N2;
    }
}

extern "C" void kernel_launch(void* const* d_in, const int* in_sizes, int n_in,
                              void* d_out, int out_size) {
    (void)in_sizes; (void)n_in; (void)out_size;
    const float* heatmaps = (const float*)d_in[0];
    float* out = (float*)d_out;

    heatmap_peaks_kernel<<<NBLOCKS, TPB>>>(heatmaps, out);
}

// round 12
// speedup vs baseline: 1.2822x; 1.0050x over previous
#include <cuda_runtime.h>
#include <math_constants.h>
#include <cstdint>

// Fixed problem shape: [16, 17, 384, 384] fp32
#define HM_W 384
#define HM_H 384
#define HM_PLANES 272
#define BAND 24
#define BANDS (HM_H / BAND)            // 16
#define TPB 128                        // 4 warps
#define ROWS_PER_WARP (BAND / 4)       // 6
#define TILE_ROWS (BAND + 2)           // 26 (band + top/bottom halo)
#define NBLOCKS (HM_PLANES * BANDS)    // 4352
#define NCHUNK 4

#define SIG_THRESH 0.05f
// logit(0.05): sigmoid(x) > 0.05  <=>  x > LOGIT_THRESH
#define LOGIT_THRESH (-2.9444389791664403f)
#define FULLM 0xffffffffu

__device__ __forceinline__ float max3(float a, float b, float c) {
    return fmaxf(a, fmaxf(b, c));
}

__device__ __forceinline__ float4 max3v(const float4& a, const float4& b, const float4& c) {
    float4 r;
    r.x = max3(a.x, b.x, c.x);
    r.y = max3(a.y, b.y, c.y);
    r.z = max3(a.z, b.z, c.z);
    r.w = max3(a.w, b.w, c.w);
    return r;
}

// peak score: sigmoid(x) if (3x3 max == x) && x > logit(0.05), else 0
__device__ __forceinline__ float peak(float m, float x) {
    float e = __expf(-x);
    float s = __fdividef(1.0f, 1.0f + e);
    return (m == x && x > LOGIT_THRESH) ? s : 0.0f;
}

__device__ __forceinline__ float4 peaks4(const float4& c, const float4& v,
                                         float vl, float vr) {
    float4 r;
    r.x = peak(max3(vl,  v.x, v.y), c.x);
    r.y = peak(max3(v.x, v.y, v.z), c.y);
    r.z = peak(max3(v.y, v.z, v.w), c.z);
    r.w = peak(max3(v.z, v.w, vr),  c.w);
    return r;
}

__device__ __forceinline__ uint32_t smem_u32(const void* p) {
    uint32_t a;
    asm("{ .reg .u64 t; cvta.to.shared.u64 t, %1; cvt.u32.u64 %0, t; }"
        : "=r"(a) : "l"(p));
    return a;
}

__device__ __forceinline__ void mbar_wait0(uint32_t mbar_a) {
    uint32_t done;
    asm volatile(
        "{\n\t"
        ".reg .pred q;\n\t"
        "mbarrier.try_wait.parity.acquire.cta.shared::cta.b64 q, [%1], 0;\n\t"
        "selp.b32 %0, 1, 0, q;\n\t"
        "}"
        : "=r"(done) : "r"(mbar_a) : "memory");
    while (!done) {
        asm volatile(
            "{\n\t"
            ".reg .pred q;\n\t"
            "mbarrier.try_wait.parity.acquire.cta.shared::cta.b64 q, [%1], 0, 0x989680;\n\t"
            "selp.b32 %0, 1, 0, q;\n\t"
            "}"
            : "=r"(done) : "r"(mbar_a) : "memory");
    }
}

// chunk c covers tile slots [CHUNK_S[c], CHUNK_E[c]]
__constant__ const int kChunkS[NCHUNK] = {0, 8, 14, 20};
__constant__ const int kChunkE[NCHUNK] = {7, 13, 19, 25};

__global__ __launch_bounds__(TPB)
void heatmap_peaks_kernel(const float* __restrict__ in, float* __restrict__ out) {
    __shared__ __align__(16) float tile[TILE_ROWS * HM_W];  // 39936 B
    __shared__ __align__(8) uint64_t mbar[NCHUNK];

    const int tid  = threadIdx.x;
    const int lane = tid & 31;
    const int warp = tid >> 5;

    const int plane = blockIdx.x / BANDS;
    const int band  = blockIdx.x - plane * BANDS;
    const int r0    = band * BAND;

    const float* __restrict__ p = in  + (size_t)plane * (HM_W * HM_H);
    float* __restrict__       o = out + (size_t)plane * (HM_W * HM_H);

    if (tid == 0) {
        #pragma unroll
        for (int c = 0; c < NCHUNK; ++c) {
            asm volatile("mbarrier.init.shared.b64 [%0], %1;"
                         :: "r"(smem_u32(&mbar[c])), "r"(1) : "memory");
        }
    }
    __syncthreads();

    if (tid == 0) {
        #pragma unroll
        for (int c = 0; c < NCHUNK; ++c) {
            // tile slot s holds global row (r0 - 1 + s); clamp to [0, HM_H-1]
            int gs = r0 - 1 + kChunkS[c];
            int ge = r0 - 1 + kChunkE[c];
            if (gs < 0) gs = 0;
            if (ge > HM_H - 1) ge = HM_H - 1;
            const int nrows = ge - gs + 1;
            const uint32_t bytes = (uint32_t)nrows * HM_W * sizeof(float);
            const int slot = gs - (r0 - 1);
            const uint32_t mb = smem_u32(&mbar[c]);
            const uint32_t dst = smem_u32(&tile[slot * HM_W]);
            asm volatile("mbarrier.arrive.expect_tx.shared.b64 _, [%0], %1;"
                         :: "r"(mb), "r"(bytes) : "memory");
            asm volatile("cp.async.bulk.shared::cluster.global.mbarrier::complete_tx::bytes "
                         "[%0], [%1], %2, [%3];"
                         :: "r"(dst), "l"(p + (size_t)gs * HM_W), "r"(bytes), "r"(mb)
                         : "memory");
        }
    }

    // Warp w consumes tile slots [6w, 6w+7]:
    //   warp0 -> chunk0; warp1 -> chunks0,1; warp2 -> chunks1,2; warp3 -> chunks2,3
    if (warp == 0) {
        mbar_wait0(smem_u32(&mbar[0]));
    } else if (warp == 1) {
        mbar_wait0(smem_u32(&mbar[0]));
        mbar_wait0(smem_u32(&mbar[1]));
    } else if (warp == 2) {
        mbar_wait0(smem_u32(&mbar[1]));
        mbar_wait0(smem_u32(&mbar[2]));
    } else {
        mbar_wait0(smem_u32(&mbar[2]));
        mbar_wait0(smem_u32(&mbar[3]));
    }

    // ---- compute from SMEM: warp w handles rows [r0+6w, r0+6w+6) ----
    const int wr = r0 + ROWS_PER_WARP * warp;        // first output row of this warp
    const int baseSlot = ROWS_PER_WARP * warp;       // smem slot of row wr-1
    const int xb = lane * 4;                         // interleaved: cols xb, xb+128, xb+256
    const float NEG = -CUDART_INF_F;
    const float4 NEG4 = make_float4(NEG, NEG, NEG, NEG);

    float4 P0, P1, P2, C0, C1, C2;
    if (wr > 0) {
        const float* t = &tile[baseSlot * HM_W + xb];
        P0 = *(const float4*)(t);
        P1 = *(const float4*)(t + 128);
        P2 = *(const float4*)(t + 256);
    } else {
        P0 = NEG4; P1 = NEG4; P2 = NEG4;
    }
    {
        const float* t = &tile[(baseSlot + 1) * HM_W + xb];
        C0 = *(const float4*)(t);
        C1 = *(const float4*)(t + 128);
        C2 = *(const float4*)(t + 256);
    }

    float* op = o + (size_t)wr * HM_W + xb;

    #pragma unroll
    for (int i = 0; i < ROWS_PER_WARP; ++i) {
        const int row = wr + i;

        float4 N0, N1, N2;
        if (row + 1 < HM_H) {
            const float* t = &tile[(baseSlot + 2 + i) * HM_W + xb];
            N0 = *(const float4*)(t);
            N1 = *(const float4*)(t + 128);
            N2 = *(const float4*)(t + 256);
        } else {
            N0 = NEG4; N1 = NEG4; N2 = NEG4;
        }

        // Vertical 3-max per column
        float4 v0 = max3v(P0, C0, N0);
        float4 v1 = max3v(P1, C1, N1);
        float4 v2 = max3v(P2, C2, N2);

        // Horizontal neighbors via warp shuffles
        float l0 = __shfl_up_sync(FULLM, v0.w, 1);
        float l1 = __shfl_up_sync(FULLM, v1.w, 1);
        float l2 = __shfl_up_sync(FULLM, v2.w, 1);
        float b01 = __shfl_sync(FULLM, v0.w, 31);
        float b12 = __shfl_sync(FULLM, v1.w, 31);
        float r0s = __shfl_down_sync(FULLM, v0.x, 1);
        float r1s = __shfl_down_sync(FULLM, v1.x, 1);
        float r2s = __shfl_down_sync(FULLM, v2.x, 1);
        float f10 = __shfl_sync(FULLM, v1.x, 0);
        float f21 = __shfl_sync(FULLM, v2.x, 0);

        if (lane == 0)  { l0 = NEG; l1 = b01; l2 = b12; }
        if (lane == 31) { r0s = f10; r1s = f21; r2s = NEG; }

        // Peak test + sigmoid, store row
        float4 o0 = peaks4(C0, v0, l0, r0s);
        float4 o1 = peaks4(C1, v1, l1, r1s);
        float4 o2 = peaks4(C2, v2, l2, r2s);

        *(float4*)(op)       = o0;
        *(float4*)(op + 128) = o1;
        *(float4*)(op + 256) = o2;
        op += HM_W;

        // Rotate carried rows
        P0 = C0; P1 = C1; P2 = C2;
        C0 = N0; C1 = N1; C2 = N2;
    }
}

extern "C" void kernel_launch(void* const* d_in, const int* in_sizes, int n_in,
                              void* d_out, int out_size) {
    (void)in_sizes; (void)n_in; (void)out_size;
    const float* heatmaps = (const float*)d_in[0];
    float* out = (float*)d_out;

    heatmap_peaks_kernel<<<NBLOCKS, TPB>>>(heatmaps, out);
}

// round 13
// speedup vs baseline: 1.2830x; 1.0006x over previous
#include <cuda_runtime.h>
#include <math_constants.h>
#include <cstdint>

// Fixed problem shape: [16, 17, 384, 384] fp32
#define HM_W 384
#define HM_H 384
#define HM_PLANES 272
#define BAND 16
#define BANDS (HM_H / BAND)            // 24
#define TPB 128                        // 4 warps
#define ROWS_PER_WARP (BAND / 4)       // 4
#define TILE_ROWS (BAND + 2)           // 18 (band + top/bottom halo)
#define NBLOCKS (HM_PLANES * BANDS)    // 6528

#define SIG_THRESH 0.05f
// logit(0.05): sigmoid(x) > 0.05  <=>  x > LOGIT_THRESH
#define LOGIT_THRESH (-2.9444389791664403f)
#define FULLM 0xffffffffu

__device__ __forceinline__ float max3(float a, float b, float c) {
    return fmaxf(a, fmaxf(b, c));
}

__device__ __forceinline__ float4 max3v(const float4& a, const float4& b, const float4& c) {
    float4 r;
    r.x = max3(a.x, b.x, c.x);
    r.y = max3(a.y, b.y, c.y);
    r.z = max3(a.z, b.z, c.z);
    r.w = max3(a.w, b.w, c.w);
    return r;
}

// peak score: sigmoid(x) if (3x3 max == x) && x > logit(0.05), else 0
__device__ __forceinline__ float peak(float m, float x) {
    float e = __expf(-x);
    float s = __fdividef(1.0f, 1.0f + e);
    return (m == x && x > LOGIT_THRESH) ? s : 0.0f;
}

__device__ __forceinline__ float4 peaks4(const float4& c, const float4& v,
                                         float vl, float vr) {
    float4 r;
    r.x = peak(max3(vl,  v.x, v.y), c.x);
    r.y = peak(max3(v.x, v.y, v.z), c.y);
    r.z = peak(max3(v.y, v.z, v.w), c.z);
    r.w = peak(max3(v.z, v.w, vr),  c.w);
    return r;
}

__device__ __forceinline__ uint32_t smem_u32(const void* p) {
    uint32_t a;
    asm("{ .reg .u64 t; cvta.to.shared.u64 t, %1; cvt.u32.u64 %0, t; }"
        : "=r"(a) : "l"(p));
    return a;
}

__global__ __launch_bounds__(TPB, 7)
void heatmap_peaks_kernel(const float* __restrict__ in, float* __restrict__ out) {
    __shared__ __align__(16) float tile[TILE_ROWS * HM_W];  // 27648 B
    __shared__ uint64_t mbar;

    const int tid  = threadIdx.x;
    const int lane = tid & 31;
    const int warp = tid >> 5;

    const int plane = blockIdx.x / BANDS;
    const int band  = blockIdx.x - plane * BANDS;
    const int r0    = band * BAND;

    const float* __restrict__ p = in  + (size_t)plane * (HM_W * HM_H);
    float* __restrict__       o = out + (size_t)plane * (HM_W * HM_H);

    // Contiguous copy range: rows [rs, re] of this plane (band + available halo)
    const int rs = (r0 > 0) ? (r0 - 1) : 0;
    const int re_ = r0 + BAND;                       // bottom halo row
    const int re = (re_ < HM_H) ? re_ : (HM_H - 1);
    const int nrows = re - rs + 1;
    const int slot0 = rs - (r0 - 1);                 // 0 normally, 1 for the top band
    const uint32_t bytes = (uint32_t)nrows * HM_W * sizeof(float);

    const uint32_t mbar_a = smem_u32(&mbar);
    const uint32_t dst_a  = smem_u32(&tile[slot0 * HM_W]);

    if (tid == 0) {
        asm volatile("mbarrier.init.shared.b64 [%0], %1;"
                     :: "r"(mbar_a), "r"(1) : "memory");
    }
    __syncthreads();

    if (tid == 0) {
        asm volatile("mbarrier.arrive.expect_tx.shared.b64 _, [%0], %1;"
                     :: "r"(mbar_a), "r"(bytes) : "memory");
        asm volatile("cp.async.bulk.shared::cluster.global.mbarrier::complete_tx::bytes "
                     "[%0], [%1], %2, [%3];"
                     :: "r"(dst_a), "l"(p + (size_t)rs * HM_W), "r"(bytes), "r"(mbar_a)
                     : "memory");
    }

    // Wait for the bulk copy (phase 0)
    {
        uint32_t done;
        asm volatile(
            "{\n\t"
            ".reg .pred q;\n\t"
            "mbarrier.try_wait.parity.acquire.cta.shared::cta.b64 q, [%1], 0;\n\t"
            "selp.b32 %0, 1, 0, q;\n\t"
            "}"
            : "=r"(done) : "r"(mbar_a) : "memory");
        while (!done) {
            asm volatile(
                "{\n\t"
                ".reg .pred q;\n\t"
                "mbarrier.try_wait.parity.acquire.cta.shared::cta.b64 q, [%1], 0, 0x989680;\n\t"
                "selp.b32 %0, 1, 0, q;\n\t"
                "}"
                : "=r"(done) : "r"(mbar_a) : "memory");
        }
    }

    // ---- compute from SMEM: warp w handles rows [r0+4w, r0+4w+4) ----
    const int wr = r0 + ROWS_PER_WARP * warp;        // first output row of this warp
    const int baseSlot = ROWS_PER_WARP * warp;       // smem slot of row wr-1
    const int xb = lane * 4;                         // interleaved: cols xb, xb+128, xb+256
    const float NEG = -CUDART_INF_F;
    const float4 NEG4 = make_float4(NEG, NEG, NEG, NEG);

    float4 P0, P1, P2, C0, C1, C2;
    if (wr > 0) {
        const float* t = &tile[baseSlot * HM_W + xb];
        P0 = *(const float4*)(t);
        P1 = *(const float4*)(t + 128);
        P2 = *(const float4*)(t + 256);
    } else {
        P0 = NEG4; P1 = NEG4; P2 = NEG4;
    }
    {
        const float* t = &tile[(baseSlot + 1) * HM_W + xb];
        C0 = *(const float4*)(t);
        C1 = *(const float4*)(t + 128);
        C2 = *(const float4*)(t + 256);
    }

    float* op = o + (size_t)wr * HM_W + xb;

    #pragma unroll
    for (int i = 0; i < ROWS_PER_WARP; ++i) {
        const int row = wr + i;

        float4 N0, N1, N2;
        if (row + 1 < HM_H) {
            const float* t = &tile[(baseSlot + 2 + i) * HM_W + xb];
            N0 = *(const float4*)(t);
            N1 = *(const float4*)(t + 128);
            N2 = *(const float4*)(t + 256);
        } else {
            N0 = NEG4; N1 = NEG4; N2 = NEG4;
        }

        // Vertical 3-max per column
        float4 v0 = max3v(P0, C0, N0);
        float4 v1 = max3v(P1, C1, N1);
        float4 v2 = max3v(P2, C2, N2);

        // Horizontal neighbors via warp shuffles
        float l0 = __shfl_up_sync(FULLM, v0.w, 1);
        float l1 = __shfl_up_sync(FULLM, v1.w, 1);
        float l2 = __shfl_up_sync(FULLM, v2.w, 1);
        float b01 = __shfl_sync(FULLM, v0.w, 31);
        float b12 = __shfl_sync(FULLM, v1.w, 31);
        float r0s = __shfl_down_sync(FULLM, v0.x, 1);
        float r1s = __shfl_down_sync(FULLM, v1.x, 1);
        float r2s = __shfl_down_sync(FULLM, v2.x, 1);
        float f10 = __shfl_sync(FULLM, v1.x, 0);
        float f21 = __shfl_sync(FULLM, v2.x, 0);

        if (lane == 0)  { l0 = NEG; l1 = b01; l2 = b12; }
        if (lane == 31) { r0s = f10; r1s = f21; r2s = NEG; }

        // Peak test + sigmoid, store row
        float4 o0 = peaks4(C0, v0, l0, r0s);
        float4 o1 = peaks4(C1, v1, l1, r1s);
        float4 o2 = peaks4(C2, v2, l2, r2s);

        *(float4*)(op)       = o0;
        *(float4*)(op + 128) = o1;
        *(float4*)(op + 256) = o2;
        op += HM_W;

        // Rotate carried rows
        P0 = C0; P1 = C1; P2 = C2;
        C0 = N0; C1 = N1; C2 = N2;
    }
}

extern "C" void kernel_launch(void* const* d_in, const int* in_sizes, int n_in,
                              void* d_out, int out_size) {
    (void)in_sizes; (void)n_in; (void)out_size;
    const float* heatmaps = (const float*)d_in[0];
    float* out = (float*)d_out;

    heatmap_peaks_kernel<<<NBLOCKS, TPB>>>(heatmaps, out);
}